// round 1
// baseline (speedup 1.0000x reference)
#include <cuda_runtime.h>
#include <cuda_bf16.h>
#include <math.h>

// ---------------------------------------------------------------------------
// Problem constants
// ---------------------------------------------------------------------------
#define Bc 2
#define Tc 4096
#define Dc 2048
#define Hc 16
#define HDc 128
#define Mc (Bc * Tc)          // 8192
#define BHc (Bc * Hc)         // 32
#define BHTc (Bc * Hc * Tc)   // 131072

// OFFSET = -log(sqrt(D)) + 1e-6
#define OFFSETc (-3.812308493079699f)

// ---------------------------------------------------------------------------
// Device scratch (allocation-free rule: __device__ globals)
// ---------------------------------------------------------------------------
__device__ float g_q [Mc * Dc];
__device__ float g_k [Mc * Dc];
__device__ float g_v [Mc * Dc];
__device__ float g_qp[Mc * Dc];
__device__ float g_kp[Mc * Dc];
__device__ float g_at[Mc * Dc];
__device__ float g_dot[BHTc];

// ---------------------------------------------------------------------------
// SGEMM: C[M,N] = A[M,K] @ B[K,N], row-major, optional exp(x+OFFSET) epilogue.
// BM=128, BN=128, BK=16, 256 threads, 8x8 per-thread microtile.
// All dims are multiples of the tiles; no bounds checks needed.
// ---------------------------------------------------------------------------
#define BM 128
#define BN 128
#define BK 16

template <bool DO_EXP>
__global__ __launch_bounds__(256, 2)
void sgemm_kernel(const float* __restrict__ A,
                  const float* __restrict__ Bm,
                  float* __restrict__ C,
                  int Mdim, int Ndim, int Kdim)
{
    __shared__ float As[BK][BM + 4];   // +4 pad: reduce transpose-store conflicts
    __shared__ float Bs[BK][BN];

    const int tid = threadIdx.x;
    const int tx  = tid & 15;          // 0..15 -> output col group
    const int ty  = tid >> 4;          // 0..15 -> output row group

    const int blockRow = blockIdx.y * BM;
    const int blockCol = blockIdx.x * BN;

    // A-tile loader mapping: 128 rows x 16 cols = 512 float4; 2 per thread.
    const int aRow = tid >> 2;         // 0..63
    const int aC4  = tid & 3;          // 0..3  (float4 column within row)
    // B-tile loader mapping: 16 rows x 128 cols = 512 float4; 2 per thread.
    const int bRow = tid >> 5;         // 0..7
    const int bC4  = tid & 31;         // 0..31

    float acc[8][8];
    #pragma unroll
    for (int i = 0; i < 8; i++)
        #pragma unroll
        for (int j = 0; j < 8; j++)
            acc[i][j] = 0.0f;

    for (int k0 = 0; k0 < Kdim; k0 += BK) {
        // ---- load A tile (transposed into As[k][m]) ----
        #pragma unroll
        for (int r = 0; r < 2; r++) {
            const int row = aRow + r * 64;
            const float4 va = *reinterpret_cast<const float4*>(
                &A[(size_t)(blockRow + row) * Kdim + k0 + aC4 * 4]);
            As[aC4 * 4 + 0][row] = va.x;
            As[aC4 * 4 + 1][row] = va.y;
            As[aC4 * 4 + 2][row] = va.z;
            As[aC4 * 4 + 3][row] = va.w;
        }
        // ---- load B tile ----
        #pragma unroll
        for (int r = 0; r < 2; r++) {
            const int row = bRow + r * 8;
            *reinterpret_cast<float4*>(&Bs[row][bC4 * 4]) =
                *reinterpret_cast<const float4*>(
                    &Bm[(size_t)(k0 + row) * Ndim + blockCol + bC4 * 4]);
        }
        __syncthreads();

        #pragma unroll
        for (int kk = 0; kk < BK; kk++) {
            float a[8], b[8];
            const float4 a0 = *reinterpret_cast<const float4*>(&As[kk][ty * 8]);
            const float4 a1 = *reinterpret_cast<const float4*>(&As[kk][ty * 8 + 4]);
            const float4 b0 = *reinterpret_cast<const float4*>(&Bs[kk][tx * 8]);
            const float4 b1 = *reinterpret_cast<const float4*>(&Bs[kk][tx * 8 + 4]);
            a[0]=a0.x; a[1]=a0.y; a[2]=a0.z; a[3]=a0.w;
            a[4]=a1.x; a[5]=a1.y; a[6]=a1.z; a[7]=a1.w;
            b[0]=b0.x; b[1]=b0.y; b[2]=b0.z; b[3]=b0.w;
            b[4]=b1.x; b[5]=b1.y; b[6]=b1.z; b[7]=b1.w;
            #pragma unroll
            for (int i = 0; i < 8; i++)
                #pragma unroll
                for (int j = 0; j < 8; j++)
                    acc[i][j] = fmaf(a[i], b[j], acc[i][j]);
        }
        __syncthreads();
    }

    // ---- epilogue ----
    #pragma unroll
    for (int i = 0; i < 8; i++) {
        const int gr = blockRow + ty * 8 + i;
        float* crow = &C[(size_t)gr * Ndim + blockCol + tx * 8];
        float4 o0, o1;
        if (DO_EXP) {
            o0.x = __expf(acc[i][0] + OFFSETc);
            o0.y = __expf(acc[i][1] + OFFSETc);
            o0.z = __expf(acc[i][2] + OFFSETc);
            o0.w = __expf(acc[i][3] + OFFSETc);
            o1.x = __expf(acc[i][4] + OFFSETc);
            o1.y = __expf(acc[i][5] + OFFSETc);
            o1.z = __expf(acc[i][6] + OFFSETc);
            o1.w = __expf(acc[i][7] + OFFSETc);
        } else {
            o0.x = acc[i][0]; o0.y = acc[i][1]; o0.z = acc[i][2]; o0.w = acc[i][3];
            o1.x = acc[i][4]; o1.y = acc[i][5]; o1.z = acc[i][6]; o1.w = acc[i][7];
        }
        *reinterpret_cast<float4*>(crow)     = o0;
        *reinterpret_cast<float4*>(crow + 4) = o1;
    }
}

// ---------------------------------------------------------------------------
// dot[b,h,t] = sum_d qp[b,t,h*HD+d] * kp[b,t,h*HD+d]
// one warp per (b,h,t); dot stored at index (b*H+h)*T + t
// ---------------------------------------------------------------------------
__global__ __launch_bounds__(256)
void dot_kernel(const float* __restrict__ qp, const float* __restrict__ kp,
                float* __restrict__ dot)
{
    const int warp = (blockIdx.x << 3) | (threadIdx.x >> 5);
    const int lane = threadIdx.x & 31;
    // warp = (b*H + h)*T + t
    const int t  = warp % Tc;
    const int h  = (warp / Tc) % Hc;
    const int b  = warp / (Tc * Hc);

    const size_t base = (size_t)(b * Tc + t) * Dc + h * HDc;
    float s = 0.0f;
    #pragma unroll
    for (int j = 0; j < HDc; j += 32)
        s = fmaf(qp[base + lane + j], kp[base + lane + j], s);

    #pragma unroll
    for (int off = 16; off > 0; off >>= 1)
        s += __shfl_down_sync(0xffffffffu, s, off);

    if (lane == 0) dot[warp] = s;
}

// ---------------------------------------------------------------------------
// Scan: att[b,h,t,d] = (cumsum_t dot[b,h,t]*v[b,t,h*HD+d]) / kp[b,t,h*HD+d]
// written in merged-head layout attn[b,t,h*HD+d]. One block per (b,h),
// 128 threads (one per d); dot tiles staged through smem.
// ---------------------------------------------------------------------------
__global__ __launch_bounds__(128)
void scan_kernel(const float* __restrict__ dot, const float* __restrict__ v,
                 const float* __restrict__ kp, float* __restrict__ attn)
{
    const int bh = blockIdx.x;
    const int b  = bh / Hc;
    const int h  = bh % Hc;
    const int d  = threadIdx.x;

    __shared__ float sdot[128];
    const float* dptr = dot + (size_t)bh * Tc;

    float s = 0.0f;
    for (int t0 = 0; t0 < Tc; t0 += 128) {
        __syncthreads();
        sdot[d] = dptr[t0 + d];
        __syncthreads();
        #pragma unroll 8
        for (int tt = 0; tt < 128; tt++) {
            const int t = t0 + tt;
            const size_t idx = (size_t)(b * Tc + t) * Dc + h * HDc + d;
            s = fmaf(sdot[tt], v[idx], s);
            attn[idx] = s / kp[idx];
        }
    }
}

// ---------------------------------------------------------------------------
// kernel_launch
// inputs: 0=hidden_states 1=Wq 2=Wk 3=Wv 4=Wo 5=Fq 6=Fk ; out: [B,T,D] f32
// ---------------------------------------------------------------------------
extern "C" void kernel_launch(void* const* d_in, const int* in_sizes, int n_in,
                              void* d_out, int out_size)
{
    (void)in_sizes; (void)n_in; (void)out_size;
    const float* x  = (const float*)d_in[0];
    const float* wq = (const float*)d_in[1];
    const float* wk = (const float*)d_in[2];
    const float* wv = (const float*)d_in[3];
    const float* wo = (const float*)d_in[4];
    const float* fq = (const float*)d_in[5];
    const float* fk = (const float*)d_in[6];
    float* out = (float*)d_out;

    float *q, *k, *v, *qp, *kp, *at, *dt;
    cudaGetSymbolAddress((void**)&q,  g_q);
    cudaGetSymbolAddress((void**)&k,  g_k);
    cudaGetSymbolAddress((void**)&v,  g_v);
    cudaGetSymbolAddress((void**)&qp, g_qp);
    cudaGetSymbolAddress((void**)&kp, g_kp);
    cudaGetSymbolAddress((void**)&at, g_at);
    cudaGetSymbolAddress((void**)&dt, g_dot);

    const dim3 tpb(256);
    const dim3 gg(Dc / BN, Mc / BM);   // (16, 64)

    // q, k, v projections
    sgemm_kernel<false><<<gg, tpb>>>(x, wq, q, Mc, Dc, Dc);
    sgemm_kernel<false><<<gg, tpb>>>(x, wk, k, Mc, Dc, Dc);
    sgemm_kernel<false><<<gg, tpb>>>(x, wv, v, Mc, Dc, Dc);

    // feature maps with fused exp(+OFFSET)
    sgemm_kernel<true><<<gg, tpb>>>(q, fq, qp, Mc, Dc, Dc);
    sgemm_kernel<true><<<gg, tpb>>>(k, fk, kp, Mc, Dc, Dc);

    // per-(b,h,t) feature dot
    dot_kernel<<<BHTc / 8, 256>>>(qp, kp, dt);

    // causal linear-attention scan + normalization (merged-head layout)
    scan_kernel<<<BHc, 128>>>(dt, v, kp, at);

    // output projection
    sgemm_kernel<false><<<gg, tpb>>>(at, wo, out, Mc, Dc, Dc);
}

// round 5
// speedup vs baseline: 3.0704x; 3.0704x over previous
#include <cuda_runtime.h>
#include <cuda_bf16.h>
#include <cstdint>
#include <stdint.h>

// ---------------------------------------------------------------------------
// Problem constants
// ---------------------------------------------------------------------------
#define Bc 2
#define Tc 4096
#define Dc 2048
#define Hc 16
#define HDc 128
#define Mc (Bc * Tc)          // 8192
#define BHc (Bc * Hc)         // 32
#define BHTc (Bc * Hc * Tc)   // 131072
#define MK (Mc * Dc)          // 16777216
#define KN (Dc * Dc)          // 4194304
#define OFFSETc (-3.812308493079699f)

// scan chunking
#define CT 64
#define CL (Tc / CT)          // 64

// GEMM tiling: 128x128 CTA tile, K-chunk 64 (halves), double buffered
#define NSTEP 32              // 2048 / 64
#define STAGE_BYTES 65536     // 4 regions x 16KB (Ahi, Alo, Bhi, Blo)
#define SMEM_SZ (2 * STAGE_BYTES + 128)

// ---------------------------------------------------------------------------
// Device scratch
// ---------------------------------------------------------------------------
__device__ uint4 g_xhi [MK / 8], g_xlo [MK / 8];
__device__ uint4 g_qhi [MK / 8], g_qlo [MK / 8];
__device__ uint4 g_khi [MK / 8], g_klo [MK / 8];
__device__ uint4 g_athi[MK / 8], g_atlo[MK / 8];
__device__ uint4 g_wthi[6 * KN / 8], g_wtlo[6 * KN / 8];
__device__ uint4 g_v4 [MK / 4];
__device__ uint4 g_qp4[MK / 4];
__device__ uint4 g_kp4[MK / 4];
__device__ float g_dot[BHTc];
__device__ float g_part[BHc * CT * HDc];

// ---------------------------------------------------------------------------
// PTX helpers (all sm_80+; no tcgen05 anywhere)
// ---------------------------------------------------------------------------
__device__ __forceinline__ uint32_t smem_u32(const void* p) {
    uint32_t a;
    asm("{ .reg .u64 t; cvta.to.shared.u64 t, %1; cvt.u32.u64 %0, t; }"
        : "=r"(a) : "l"(p));
    return a;
}

__device__ __forceinline__ void cp16(uint32_t dst, const void* src) {
    asm volatile("cp.async.cg.shared.global [%0], [%1], 16;"
                 :: "r"(dst), "l"(src));
}
__device__ __forceinline__ void cp_commit() {
    asm volatile("cp.async.commit_group;" ::: "memory");
}
template <int N>
__device__ __forceinline__ void cp_wait() {
    asm volatile("cp.async.wait_group %0;" :: "n"(N) : "memory");
}

__device__ __forceinline__ void ldsm_x4(uint32_t* r, uint32_t addr) {
    asm volatile("ldmatrix.sync.aligned.m8n8.x4.shared.b16 {%0,%1,%2,%3}, [%4];"
        : "=r"(r[0]), "=r"(r[1]), "=r"(r[2]), "=r"(r[3]) : "r"(addr));
}

__device__ __forceinline__ void mma16816(float* d, const uint32_t* a,
                                         uint32_t b0, uint32_t b1) {
    asm volatile("mma.sync.aligned.m16n8k16.row.col.f32.bf16.bf16.f32 "
        "{%0,%1,%2,%3}, {%4,%5,%6,%7}, {%8,%9}, {%0,%1,%2,%3};"
        : "+f"(d[0]), "+f"(d[1]), "+f"(d[2]), "+f"(d[3])
        : "r"(a[0]), "r"(a[1]), "r"(a[2]), "r"(a[3]), "r"(b0), "r"(b1));
}

// ---------------------------------------------------------------------------
// mma.sync GEMM: C[8192, 2048] = A[8192, 2048] @ B^T where B is [2048 rows=N][2048=K]
//   A bf16 hi/lo row-major (K contiguous); B bf16 hi/lo [N][K] (pre-transposed).
//   3-product hi/lo split with fp32 accumulators.
// MODE 0: C fp32   MODE 1: C = exp(C + OFFSET) fp32   MODE 2: C -> bf16 hi/lo
// ---------------------------------------------------------------------------
template <int MODE>
__global__ __launch_bounds__(256, 1)
void mma_gemm(const __nv_bfloat16* __restrict__ Ahi, const __nv_bfloat16* __restrict__ Alo,
              const __nv_bfloat16* __restrict__ Bhi, const __nv_bfloat16* __restrict__ Blo,
              float* __restrict__ Cf,
              __nv_bfloat16* __restrict__ Chi, __nv_bfloat16* __restrict__ Clo)
{
    extern __shared__ char smraw[];
    const uint32_t sb = (smem_u32(smraw) + 127u) & ~127u;
    const int tid  = threadIdx.x;
    const int wid  = tid >> 5;
    const int lane = tid & 31;

    const int bm = blockIdx.y * 128;
    const int bn = blockIdx.x * 128;
    const char* pAhi = (const char*)Ahi;
    const char* pAlo = (const char*)Alo;
    const char* pBhi = (const char*)Bhi;
    const char* pBlo = (const char*)Blo;

    // Stage layout per slot: [Ahi 16K][Alo 16K][Bhi 16K][Blo 16K]
    // Each region: 128 rows x 128 bytes (64 halves), SW128 swizzle.
    auto load_stage = [&](int s, int slot) {
        const uint32_t st = sb + slot * STAGE_BYTES;
        const size_t kb = (size_t)s * 128;          // byte offset along K
        #pragma unroll
        for (int i = tid; i < 1024; i += 256) {
            const int row = i >> 3, c = i & 7;
            const uint32_t sw = ((uint32_t)row << 7) | ((uint32_t)(c ^ (row & 7)) << 4);
            const size_t gA = (size_t)(bm + row) * 4096 + kb + ((size_t)c << 4);
            const size_t gB = (size_t)(bn + row) * 4096 + kb + ((size_t)c << 4);
            cp16(st + sw,         pAhi + gA);
            cp16(st + 16384 + sw, pAlo + gA);
            cp16(st + 32768 + sw, pBhi + gB);
            cp16(st + 49152 + sw, pBlo + gB);
        }
        cp_commit();
    };

    float acc[4][4][4];
    #pragma unroll
    for (int i = 0; i < 4; i++)
        #pragma unroll
        for (int j = 0; j < 4; j++)
            #pragma unroll
            for (int k = 0; k < 4; k++)
                acc[i][j][k] = 0.0f;

    const int wm = (wid >> 2) * 64;   // warp m-offset in tile (0 or 64)
    const int wn = (wid & 3) * 32;    // warp n-offset in tile (0,32,64,96)
    const int r16 = lane & 15;
    const int ko  = lane >> 4;        // 0/1: k-half selector for ldmatrix

    load_stage(0, 0);
    load_stage(1, 1);

    for (int s = 0; s < NSTEP; s++) {
        if (s == NSTEP - 1) cp_wait<0>(); else cp_wait<1>();
        __syncthreads();
        const uint32_t st = sb + (s & 1) * STAGE_BYTES;

        #pragma unroll
        for (int ks = 0; ks < 4; ks++) {
            uint32_t ah[4][4], al[4][4], bh[2][4], bl[2][4];
            const int chunk = 2 * ks + ko;
            #pragma unroll
            for (int mi = 0; mi < 4; mi++) {
                const int row = wm + mi * 16 + r16;
                const uint32_t sw = ((uint32_t)row << 7) |
                                    ((uint32_t)(chunk ^ (row & 7)) << 4);
                ldsm_x4(ah[mi], st + sw);
                ldsm_x4(al[mi], st + 16384 + sw);
            }
            #pragma unroll
            for (int nj = 0; nj < 2; nj++) {
                const int row = wn + nj * 16 + r16;
                const uint32_t sw = ((uint32_t)row << 7) |
                                    ((uint32_t)(chunk ^ (row & 7)) << 4);
                ldsm_x4(bh[nj], st + 32768 + sw);
                ldsm_x4(bl[nj], st + 49152 + sw);
            }
            #pragma unroll
            for (int mi = 0; mi < 4; mi++) {
                #pragma unroll
                for (int ni = 0; ni < 4; ni++) {
                    const int g = ni >> 1, o = ni & 1;
                    mma16816(acc[mi][ni], ah[mi], bh[g][o], bh[g][o + 2]);
                    mma16816(acc[mi][ni], ah[mi], bl[g][o], bl[g][o + 2]);
                    mma16816(acc[mi][ni], al[mi], bh[g][o], bh[g][o + 2]);
                }
            }
        }
        __syncthreads();
        if (s + 2 < NSTEP) load_stage(s + 2, s & 1);
    }

    // ---- epilogue: acc[mi][ni] is m16n8 frag.
    // c0,c1: (m = t/4, n = 2*(t%4)+{0,1}); c2,c3: (m+8, same n)
    const int lm = lane >> 2;
    const int ln = (lane & 3) * 2;
    #pragma unroll
    for (int mi = 0; mi < 4; mi++) {
        #pragma unroll
        for (int ni = 0; ni < 4; ni++) {
            const int m0 = bm + wm + mi * 16 + lm;
            const int n0 = bn + wn + ni * 8 + ln;
            const float* a = acc[mi][ni];
            #pragma unroll
            for (int hh = 0; hh < 2; hh++) {       // row m0 / m0+8
                const size_t off = (size_t)(m0 + hh * 8) * 2048 + n0;
                float v0 = a[2 * hh], v1 = a[2 * hh + 1];
                if (MODE == 1) {
                    v0 = __expf(v0 + OFFSETc);
                    v1 = __expf(v1 + OFFSETc);
                }
                if (MODE == 2) {
                    const __nv_bfloat16 h0 = __float2bfloat16(v0);
                    const __nv_bfloat16 h1 = __float2bfloat16(v1);
                    const __nv_bfloat16 l0 = __float2bfloat16(v0 - __bfloat162float(h0));
                    const __nv_bfloat16 l1 = __float2bfloat16(v1 - __bfloat162float(h1));
                    *reinterpret_cast<__nv_bfloat162*>(Chi + off) = __halves2bfloat162(h0, h1);
                    *reinterpret_cast<__nv_bfloat162*>(Clo + off) = __halves2bfloat162(l0, l1);
                } else {
                    float2 o; o.x = v0; o.y = v1;
                    *reinterpret_cast<float2*>(Cf + off) = o;
                }
            }
        }
    }
}

// ---------------------------------------------------------------------------
// fp32 -> bf16 hi/lo elementwise split (for hidden_states)
// ---------------------------------------------------------------------------
__global__ __launch_bounds__(256)
void split_fp32(const float4* __restrict__ in,
                __nv_bfloat162* __restrict__ hi, __nv_bfloat162* __restrict__ lo,
                int n4)
{
    const int i = blockIdx.x * 256 + threadIdx.x;
    if (i >= n4) return;
    const float4 v = in[i];
    const __nv_bfloat16 h0 = __float2bfloat16(v.x), h1 = __float2bfloat16(v.y);
    const __nv_bfloat16 h2 = __float2bfloat16(v.z), h3 = __float2bfloat16(v.w);
    const __nv_bfloat16 l0 = __float2bfloat16(v.x - __bfloat162float(h0));
    const __nv_bfloat16 l1 = __float2bfloat16(v.y - __bfloat162float(h1));
    const __nv_bfloat16 l2 = __float2bfloat16(v.z - __bfloat162float(h2));
    const __nv_bfloat16 l3 = __float2bfloat16(v.w - __bfloat162float(h3));
    hi[2 * i]     = __halves2bfloat162(h0, h1);
    hi[2 * i + 1] = __halves2bfloat162(h2, h3);
    lo[2 * i]     = __halves2bfloat162(l0, l1);
    lo[2 * i + 1] = __halves2bfloat162(l2, l3);
}

// ---------------------------------------------------------------------------
// W [K,N] row-major -> W^T [N,K] bf16 hi/lo
// ---------------------------------------------------------------------------
__global__ __launch_bounds__(256)
void transpose_split(const float* __restrict__ W,
                     __nv_bfloat16* __restrict__ hiT, __nv_bfloat16* __restrict__ loT)
{
    __shared__ float tile[32][33];
    const int tx = threadIdx.x & 31, ty = threadIdx.x >> 5;
    const int n0 = blockIdx.x * 32, k0 = blockIdx.y * 32;
    #pragma unroll
    for (int j = 0; j < 32; j += 8)
        tile[ty + j][tx] = W[(size_t)(k0 + ty + j) * Dc + n0 + tx];
    __syncthreads();
    #pragma unroll
    for (int j = 0; j < 32; j += 8) {
        const float v = tile[tx][ty + j];
        const __nv_bfloat16 h = __float2bfloat16(v);
        const __nv_bfloat16 l = __float2bfloat16(v - __bfloat162float(h));
        const size_t o = (size_t)(n0 + ty + j) * Dc + (k0 + tx);
        hiT[o] = h;
        loT[o] = l;
    }
}

// ---------------------------------------------------------------------------
// dot[b,h,t] = sum_d qp * kp
// ---------------------------------------------------------------------------
__global__ __launch_bounds__(256)
void dot_kernel(const float* __restrict__ qp, const float* __restrict__ kp,
                float* __restrict__ dot)
{
    const int warp = (blockIdx.x << 3) | (threadIdx.x >> 5);
    const int lane = threadIdx.x & 31;
    const int t = warp % Tc;
    const int h = (warp / Tc) % Hc;
    const int b = warp / (Tc * Hc);
    const size_t base = (size_t)(b * Tc + t) * Dc + h * HDc;
    float s = 0.0f;
    #pragma unroll
    for (int j = 0; j < HDc; j += 32)
        s = fmaf(qp[base + lane + j], kp[base + lane + j], s);
    #pragma unroll
    for (int off = 16; off > 0; off >>= 1)
        s += __shfl_down_sync(0xffffffffu, s, off);
    if (lane == 0) dot[warp] = s;
}

// ---------------------------------------------------------------------------
// Chunked scan (3 phases). part layout: [bh][chunk][d]
// ---------------------------------------------------------------------------
__global__ __launch_bounds__(128)
void scanA(const float* __restrict__ dot, const float* __restrict__ v,
           float* __restrict__ part)
{
    const int ch = blockIdx.x, bh = blockIdx.y, d = threadIdx.x;
    const int b = bh >> 4, h = bh & 15;
    __shared__ float sdot[CL];
    if (d < CL) sdot[d] = dot[(size_t)bh * Tc + ch * CL + d];
    __syncthreads();
    float s = 0.0f;
    const size_t base = (size_t)(b * Tc + ch * CL) * Dc + h * HDc + d;
    #pragma unroll 4
    for (int tt = 0; tt < CL; tt++)
        s = fmaf(sdot[tt], v[base + (size_t)tt * Dc], s);
    part[((size_t)bh * CT + ch) * HDc + d] = s;
}

__global__ __launch_bounds__(128)
void scanB(float* __restrict__ part)
{
    const int bh = blockIdx.x, d = threadIdx.x;
    float run = 0.0f;
    for (int ch = 0; ch < CT; ch++) {
        const size_t idx = ((size_t)bh * CT + ch) * HDc + d;
        const float p = part[idx];
        part[idx] = run;
        run += p;
    }
}

__global__ __launch_bounds__(128)
void scanC(const float* __restrict__ dot, const float* __restrict__ v,
           const float* __restrict__ kp, const float* __restrict__ part,
           __nv_bfloat16* __restrict__ athi, __nv_bfloat16* __restrict__ atlo)
{
    const int ch = blockIdx.x, bh = blockIdx.y, d = threadIdx.x;
    const int b = bh >> 4, h = bh & 15;
    __shared__ float sdot[CL];
    if (d < CL) sdot[d] = dot[(size_t)bh * Tc + ch * CL + d];
    __syncthreads();
    float s = part[((size_t)bh * CT + ch) * HDc + d];
    const size_t base = (size_t)(b * Tc + ch * CL) * Dc + h * HDc + d;
    #pragma unroll 4
    for (int tt = 0; tt < CL; tt++) {
        const size_t idx = base + (size_t)tt * Dc;
        s = fmaf(sdot[tt], v[idx], s);
        const float val = s / kp[idx];
        const __nv_bfloat16 hh = __float2bfloat16(val);
        athi[idx] = hh;
        atlo[idx] = __float2bfloat16(val - __bfloat162float(hh));
    }
}

// ---------------------------------------------------------------------------
// kernel_launch
// ---------------------------------------------------------------------------
extern "C" void kernel_launch(void* const* d_in, const int* in_sizes, int n_in,
                              void* d_out, int out_size)
{
    (void)in_sizes; (void)n_in; (void)out_size;
    const float* x  = (const float*)d_in[0];
    const float* wq = (const float*)d_in[1];
    const float* wk = (const float*)d_in[2];
    const float* wv = (const float*)d_in[3];
    const float* wo = (const float*)d_in[4];
    const float* fq = (const float*)d_in[5];
    const float* fk = (const float*)d_in[6];
    float* out = (float*)d_out;

    void *xhi, *xlo, *qhi, *qlo, *khi, *klo, *athi, *atlo, *wthi, *wtlo;
    void *v4, *qp4, *kp4, *dt, *pt;
    cudaGetSymbolAddress(&xhi,  g_xhi);  cudaGetSymbolAddress(&xlo,  g_xlo);
    cudaGetSymbolAddress(&qhi,  g_qhi);  cudaGetSymbolAddress(&qlo,  g_qlo);
    cudaGetSymbolAddress(&khi,  g_khi);  cudaGetSymbolAddress(&klo,  g_klo);
    cudaGetSymbolAddress(&athi, g_athi); cudaGetSymbolAddress(&atlo, g_atlo);
    cudaGetSymbolAddress(&wthi, g_wthi); cudaGetSymbolAddress(&wtlo, g_wtlo);
    cudaGetSymbolAddress(&v4,  g_v4);
    cudaGetSymbolAddress(&qp4, g_qp4);
    cudaGetSymbolAddress(&kp4, g_kp4);
    cudaGetSymbolAddress(&dt,  g_dot);
    cudaGetSymbolAddress(&pt,  g_part);

    typedef __nv_bfloat16 bf;
    bf* WThi = (bf*)wthi;  bf* WTlo = (bf*)wtlo;
    float* vF  = (float*)v4;
    float* qpF = (float*)qp4;
    float* kpF = (float*)kp4;
    float* dotF = (float*)dt;
    float* partF = (float*)pt;

    cudaFuncSetAttribute(mma_gemm<0>, cudaFuncAttributeMaxDynamicSharedMemorySize, SMEM_SZ);
    cudaFuncSetAttribute(mma_gemm<1>, cudaFuncAttributeMaxDynamicSharedMemorySize, SMEM_SZ);
    cudaFuncSetAttribute(mma_gemm<2>, cudaFuncAttributeMaxDynamicSharedMemorySize, SMEM_SZ);

    // 1) split x, transpose+split weights
    split_fp32<<<(MK / 4 + 255) / 256, 256>>>((const float4*)x,
        (__nv_bfloat162*)xhi, (__nv_bfloat162*)xlo, MK / 4);
    const dim3 tg(Dc / 32, Dc / 32);
    transpose_split<<<tg, 256>>>(wq, WThi + 0 * (size_t)KN, WTlo + 0 * (size_t)KN);
    transpose_split<<<tg, 256>>>(wk, WThi + 1 * (size_t)KN, WTlo + 1 * (size_t)KN);
    transpose_split<<<tg, 256>>>(wv, WThi + 2 * (size_t)KN, WTlo + 2 * (size_t)KN);
    transpose_split<<<tg, 256>>>(fq, WThi + 3 * (size_t)KN, WTlo + 3 * (size_t)KN);
    transpose_split<<<tg, 256>>>(fk, WThi + 4 * (size_t)KN, WTlo + 4 * (size_t)KN);
    transpose_split<<<tg, 256>>>(wo, WThi + 5 * (size_t)KN, WTlo + 5 * (size_t)KN);

    const dim3 gg(Dc / 128, Mc / 128);   // (16, 64)

    // 2) projections
    mma_gemm<2><<<gg, 256, SMEM_SZ>>>((bf*)xhi, (bf*)xlo,
        WThi + 0 * (size_t)KN, WTlo + 0 * (size_t)KN, nullptr, (bf*)qhi, (bf*)qlo);
    mma_gemm<2><<<gg, 256, SMEM_SZ>>>((bf*)xhi, (bf*)xlo,
        WThi + 1 * (size_t)KN, WTlo + 1 * (size_t)KN, nullptr, (bf*)khi, (bf*)klo);
    mma_gemm<0><<<gg, 256, SMEM_SZ>>>((bf*)xhi, (bf*)xlo,
        WThi + 2 * (size_t)KN, WTlo + 2 * (size_t)KN, vF, nullptr, nullptr);

    // 3) feature maps with fused exp
    mma_gemm<1><<<gg, 256, SMEM_SZ>>>((bf*)qhi, (bf*)qlo,
        WThi + 3 * (size_t)KN, WTlo + 3 * (size_t)KN, qpF, nullptr, nullptr);
    mma_gemm<1><<<gg, 256, SMEM_SZ>>>((bf*)khi, (bf*)klo,
        WThi + 4 * (size_t)KN, WTlo + 4 * (size_t)KN, kpF, nullptr, nullptr);

    // 4) dot + chunked scan (writes at in bf16 hi/lo)
    dot_kernel<<<BHTc / 8, 256>>>(qpF, kpF, dotF);
    scanA<<<dim3(CT, BHc), 128>>>(dotF, vF, partF);
    scanB<<<BHc, 128>>>(partF);
    scanC<<<dim3(CT, BHc), 128>>>(dotF, vF, kpF, partF, (bf*)athi, (bf*)atlo);

    // 5) output projection
    mma_gemm<0><<<gg, 256, SMEM_SZ>>>((bf*)athi, (bf*)atlo,
        WThi + 5 * (size_t)KN, WTlo + 5 * (size_t)KN, out, nullptr, nullptr);
}

// round 6
// speedup vs baseline: 3.9847x; 1.2978x over previous
#include <cuda_runtime.h>
#include <cuda_bf16.h>
#include <cstdint>
#include <stdint.h>

// ---------------------------------------------------------------------------
// Problem constants
// ---------------------------------------------------------------------------
#define Bc 2
#define Tc 4096
#define Dc 2048
#define Hc 16
#define HDc 128
#define Mc (Bc * Tc)          // 8192
#define BHc (Bc * Hc)         // 32
#define BHTc (Bc * Hc * Tc)   // 131072
#define MK (Mc * Dc)          // 16777216
#define KN (Dc * Dc)          // 4194304
#define OFFSETc (-3.812308493079699f)

// scan chunking
#define CT 64
#define CL (Tc / CT)          // 64

// GEMM tiling: 128x128 CTA tile, K-chunk 64, triple buffered
#define NSTEP 32              // 2048 / 64
#define STAGE_BYTES 65536     // 4 regions x 16KB (Ahi, Alo, Bhi, Blo)
#define SMEM_SZ (3 * STAGE_BYTES + 128)

// ---------------------------------------------------------------------------
// Device scratch
// ---------------------------------------------------------------------------
__device__ uint4 g_xhi [MK / 8], g_xlo [MK / 8];
__device__ uint4 g_qhi [KN / 8], g_qlo [KN / 8];     // W'q^T bf16 hi/lo
__device__ uint4 g_khi [KN / 8], g_klo [KN / 8];     // W'k^T bf16 hi/lo
__device__ uint4 g_athi[MK / 8], g_atlo[MK / 8];
__device__ uint4 g_wthi[6 * KN / 8], g_wtlo[6 * KN / 8];
__device__ uint4 g_v4 [MK / 4];
__device__ uint4 g_qp4[MK / 4];
__device__ uint4 g_kp4[MK / 4];
__device__ float g_dot[BHTc];
__device__ float g_part[BHc * CT * HDc];

// ---------------------------------------------------------------------------
// PTX helpers (sm_80+)
// ---------------------------------------------------------------------------
__device__ __forceinline__ uint32_t smem_u32(const void* p) {
    uint32_t a;
    asm("{ .reg .u64 t; cvta.to.shared.u64 t, %1; cvt.u32.u64 %0, t; }"
        : "=r"(a) : "l"(p));
    return a;
}

__device__ __forceinline__ void cp16(uint32_t dst, const void* src) {
    asm volatile("cp.async.cg.shared.global [%0], [%1], 16;"
                 :: "r"(dst), "l"(src));
}
__device__ __forceinline__ void cp_commit() {
    asm volatile("cp.async.commit_group;" ::: "memory");
}
template <int N>
__device__ __forceinline__ void cp_wait() {
    asm volatile("cp.async.wait_group %0;" :: "n"(N) : "memory");
}

__device__ __forceinline__ void ldsm_x4(uint32_t* r, uint32_t addr) {
    asm volatile("ldmatrix.sync.aligned.m8n8.x4.shared.b16 {%0,%1,%2,%3}, [%4];"
        : "=r"(r[0]), "=r"(r[1]), "=r"(r[2]), "=r"(r[3]) : "r"(addr));
}

__device__ __forceinline__ void mma16816(float* d, const uint32_t* a,
                                         uint32_t b0, uint32_t b1) {
    asm volatile("mma.sync.aligned.m16n8k16.row.col.f32.bf16.bf16.f32 "
        "{%0,%1,%2,%3}, {%4,%5,%6,%7}, {%8,%9}, {%0,%1,%2,%3};"
        : "+f"(d[0]), "+f"(d[1]), "+f"(d[2]), "+f"(d[3])
        : "r"(a[0]), "r"(a[1]), "r"(a[2]), "r"(a[3]), "r"(b0), "r"(b1));
}

// ---------------------------------------------------------------------------
// mma.sync GEMM: C[Mdim, 2048] = A[Mdim, 2048] @ B^T, B stored [N=2048][K=2048].
// A, B bf16 hi/lo; 3-product hi/lo split with fp32 accumulators.
// Mdim set by grid.y * 128. K fixed at 2048, N fixed at 2048.
// MODE 0: C fp32   MODE 1: C = exp(C + OFFSET) fp32   MODE 2: C -> bf16 hi/lo
// ---------------------------------------------------------------------------
template <int MODE>
__global__ __launch_bounds__(256, 1)
void mma_gemm(const __nv_bfloat16* __restrict__ Ahi, const __nv_bfloat16* __restrict__ Alo,
              const __nv_bfloat16* __restrict__ Bhi, const __nv_bfloat16* __restrict__ Blo,
              float* __restrict__ Cf,
              __nv_bfloat16* __restrict__ Chi, __nv_bfloat16* __restrict__ Clo)
{
    extern __shared__ char smraw[];
    const uint32_t sb = (smem_u32(smraw) + 127u) & ~127u;
    const int tid  = threadIdx.x;
    const int wid  = tid >> 5;
    const int lane = tid & 31;

    const int bm = blockIdx.y * 128;
    const int bn = blockIdx.x * 128;
    const char* pAhi = (const char*)Ahi;
    const char* pAlo = (const char*)Alo;
    const char* pBhi = (const char*)Bhi;
    const char* pBlo = (const char*)Blo;

    // Stage layout per slot: [Ahi 16K][Alo 16K][Bhi 16K][Blo 16K]
    // Each region: 128 rows x 128 bytes (64 halves), SW128 swizzle.
    auto load_stage = [&](int s, int slot) {
        const uint32_t st = sb + slot * STAGE_BYTES;
        const size_t kb = (size_t)s * 128;          // byte offset along K
        #pragma unroll
        for (int i = tid; i < 1024; i += 256) {
            const int row = i >> 3, c = i & 7;
            const uint32_t sw = ((uint32_t)row << 7) | ((uint32_t)(c ^ (row & 7)) << 4);
            const size_t gA = (size_t)(bm + row) * 4096 + kb + ((size_t)c << 4);
            const size_t gB = (size_t)(bn + row) * 4096 + kb + ((size_t)c << 4);
            cp16(st + sw,         pAhi + gA);
            cp16(st + 16384 + sw, pAlo + gA);
            cp16(st + 32768 + sw, pBhi + gB);
            cp16(st + 49152 + sw, pBlo + gB);
        }
        cp_commit();
    };

    float acc[4][4][4];
    #pragma unroll
    for (int i = 0; i < 4; i++)
        #pragma unroll
        for (int j = 0; j < 4; j++)
            #pragma unroll
            for (int k = 0; k < 4; k++)
                acc[i][j][k] = 0.0f;

    const int wm = (wid >> 2) * 64;   // warp m-offset (0 or 64)
    const int wn = (wid & 3) * 32;    // warp n-offset (0,32,64,96)
    const int r16 = lane & 15;
    const int ko  = lane >> 4;        // k-half selector for ldmatrix

    load_stage(0, 0);
    load_stage(1, 1);
    load_stage(2, 2);

    int slot = 0;
    for (int s = 0; s < NSTEP; s++) {
        if (s < NSTEP - 2)       cp_wait<2>();
        else if (s == NSTEP - 2) cp_wait<1>();
        else                     cp_wait<0>();
        __syncthreads();
        const uint32_t st = sb + slot * STAGE_BYTES;

        #pragma unroll
        for (int ks = 0; ks < 4; ks++) {
            uint32_t ah[4][4], al[4][4], bh[2][4], bl[2][4];
            const int chunk = 2 * ks + ko;
            #pragma unroll
            for (int mi = 0; mi < 4; mi++) {
                const int row = wm + mi * 16 + r16;
                const uint32_t sw = ((uint32_t)row << 7) |
                                    ((uint32_t)(chunk ^ (row & 7)) << 4);
                ldsm_x4(ah[mi], st + sw);
                ldsm_x4(al[mi], st + 16384 + sw);
            }
            #pragma unroll
            for (int nj = 0; nj < 2; nj++) {
                const int row = wn + nj * 16 + r16;
                const uint32_t sw = ((uint32_t)row << 7) |
                                    ((uint32_t)(chunk ^ (row & 7)) << 4);
                ldsm_x4(bh[nj], st + 32768 + sw);
                ldsm_x4(bl[nj], st + 49152 + sw);
            }
            #pragma unroll
            for (int mi = 0; mi < 4; mi++) {
                #pragma unroll
                for (int ni = 0; ni < 4; ni++) {
                    const int g = ni >> 1, o = ni & 1;
                    mma16816(acc[mi][ni], ah[mi], bh[g][o], bh[g][o + 2]);
                    mma16816(acc[mi][ni], ah[mi], bl[g][o], bl[g][o + 2]);
                    mma16816(acc[mi][ni], al[mi], bh[g][o], bh[g][o + 2]);
                }
            }
        }
        __syncthreads();
        if (s + 3 < NSTEP) load_stage(s + 3, slot);
        slot = (slot == 2) ? 0 : slot + 1;
    }

    // ---- epilogue
    const int lm = lane >> 2;
    const int ln = (lane & 3) * 2;
    #pragma unroll
    for (int mi = 0; mi < 4; mi++) {
        #pragma unroll
        for (int ni = 0; ni < 4; ni++) {
            const int m0 = bm + wm + mi * 16 + lm;
            const int n0 = bn + wn + ni * 8 + ln;
            const float* a = acc[mi][ni];
            #pragma unroll
            for (int hh = 0; hh < 2; hh++) {
                const size_t off = (size_t)(m0 + hh * 8) * 2048 + n0;
                float v0 = a[2 * hh], v1 = a[2 * hh + 1];
                if (MODE == 1) {
                    v0 = __expf(v0 + OFFSETc);
                    v1 = __expf(v1 + OFFSETc);
                }
                if (MODE == 2) {
                    const __nv_bfloat16 h0 = __float2bfloat16(v0);
                    const __nv_bfloat16 h1 = __float2bfloat16(v1);
                    const __nv_bfloat16 l0 = __float2bfloat16(v0 - __bfloat162float(h0));
                    const __nv_bfloat16 l1 = __float2bfloat16(v1 - __bfloat162float(h1));
                    *reinterpret_cast<__nv_bfloat162*>(Chi + off) = __halves2bfloat162(h0, h1);
                    *reinterpret_cast<__nv_bfloat162*>(Clo + off) = __halves2bfloat162(l0, l1);
                } else {
                    float2 o; o.x = v0; o.y = v1;
                    *reinterpret_cast<float2*>(Cf + off) = o;
                }
            }
        }
    }
}

// ---------------------------------------------------------------------------
// fp32 -> bf16 hi/lo elementwise split
// ---------------------------------------------------------------------------
__global__ __launch_bounds__(256)
void split_fp32(const float4* __restrict__ in,
                __nv_bfloat162* __restrict__ hi, __nv_bfloat162* __restrict__ lo,
                int n4)
{
    const int i = blockIdx.x * 256 + threadIdx.x;
    if (i >= n4) return;
    const float4 v = in[i];
    const __nv_bfloat16 h0 = __float2bfloat16(v.x), h1 = __float2bfloat16(v.y);
    const __nv_bfloat16 h2 = __float2bfloat16(v.z), h3 = __float2bfloat16(v.w);
    const __nv_bfloat16 l0 = __float2bfloat16(v.x - __bfloat162float(h0));
    const __nv_bfloat16 l1 = __float2bfloat16(v.y - __bfloat162float(h1));
    const __nv_bfloat16 l2 = __float2bfloat16(v.z - __bfloat162float(h2));
    const __nv_bfloat16 l3 = __float2bfloat16(v.w - __bfloat162float(h3));
    hi[2 * i]     = __halves2bfloat162(h0, h1);
    hi[2 * i + 1] = __halves2bfloat162(h2, h3);
    lo[2 * i]     = __halves2bfloat162(l0, l1);
    lo[2 * i + 1] = __halves2bfloat162(l2, l3);
}

// ---------------------------------------------------------------------------
// W [K,N] row-major -> W^T [N,K] bf16 hi/lo
// ---------------------------------------------------------------------------
__global__ __launch_bounds__(256)
void transpose_split(const float* __restrict__ W,
                     __nv_bfloat16* __restrict__ hiT, __nv_bfloat16* __restrict__ loT)
{
    __shared__ float tile[32][33];
    const int tx = threadIdx.x & 31, ty = threadIdx.x >> 5;
    const int n0 = blockIdx.x * 32, k0 = blockIdx.y * 32;
    #pragma unroll
    for (int j = 0; j < 32; j += 8)
        tile[ty + j][tx] = W[(size_t)(k0 + ty + j) * Dc + n0 + tx];
    __syncthreads();
    #pragma unroll
    for (int j = 0; j < 32; j += 8) {
        const float v = tile[tx][ty + j];
        const __nv_bfloat16 h = __float2bfloat16(v);
        const __nv_bfloat16 l = __float2bfloat16(v - __bfloat162float(h));
        const size_t o = (size_t)(n0 + ty + j) * Dc + (k0 + tx);
        hiT[o] = h;
        loT[o] = l;
    }
}

// ---------------------------------------------------------------------------
// dot[b,h,t] = sum_d qp * kp
// ---------------------------------------------------------------------------
__global__ __launch_bounds__(256)
void dot_kernel(const float* __restrict__ qp, const float* __restrict__ kp,
                float* __restrict__ dot)
{
    const int warp = (blockIdx.x << 3) | (threadIdx.x >> 5);
    const int lane = threadIdx.x & 31;
    const int t = warp % Tc;
    const int h = (warp / Tc) % Hc;
    const int b = warp / (Tc * Hc);
    const size_t base = (size_t)(b * Tc + t) * Dc + h * HDc;
    float s = 0.0f;
    #pragma unroll
    for (int j = 0; j < HDc; j += 32)
        s = fmaf(qp[base + lane + j], kp[base + lane + j], s);
    #pragma unroll
    for (int off = 16; off > 0; off >>= 1)
        s += __shfl_down_sync(0xffffffffu, s, off);
    if (lane == 0) dot[warp] = s;
}

// ---------------------------------------------------------------------------
// Chunked scan (3 phases). part layout: [bh][chunk][d]
// ---------------------------------------------------------------------------
__global__ __launch_bounds__(128)
void scanA(const float* __restrict__ dot, const float* __restrict__ v,
           float* __restrict__ part)
{
    const int ch = blockIdx.x, bh = blockIdx.y, d = threadIdx.x;
    const int b = bh >> 4, h = bh & 15;
    __shared__ float sdot[CL];
    if (d < CL) sdot[d] = dot[(size_t)bh * Tc + ch * CL + d];
    __syncthreads();
    float s = 0.0f;
    const size_t base = (size_t)(b * Tc + ch * CL) * Dc + h * HDc + d;
    #pragma unroll 4
    for (int tt = 0; tt < CL; tt++)
        s = fmaf(sdot[tt], v[base + (size_t)tt * Dc], s);
    part[((size_t)bh * CT + ch) * HDc + d] = s;
}

__global__ __launch_bounds__(128)
void scanB(float* __restrict__ part)
{
    const int bh = blockIdx.x, d = threadIdx.x;
    float run = 0.0f;
    for (int ch = 0; ch < CT; ch++) {
        const size_t idx = ((size_t)bh * CT + ch) * HDc + d;
        const float p = part[idx];
        part[idx] = run;
        run += p;
    }
}

__global__ __launch_bounds__(128)
void scanC(const float* __restrict__ dot, const float* __restrict__ v,
           const float* __restrict__ kp, const float* __restrict__ part,
           __nv_bfloat16* __restrict__ athi, __nv_bfloat16* __restrict__ atlo)
{
    const int ch = blockIdx.x, bh = blockIdx.y, d = threadIdx.x;
    const int b = bh >> 4, h = bh & 15;
    __shared__ float sdot[CL];
    if (d < CL) sdot[d] = dot[(size_t)bh * Tc + ch * CL + d];
    __syncthreads();
    float s = part[((size_t)bh * CT + ch) * HDc + d];
    const size_t base = (size_t)(b * Tc + ch * CL) * Dc + h * HDc + d;
    #pragma unroll 4
    for (int tt = 0; tt < CL; tt++) {
        const size_t idx = base + (size_t)tt * Dc;
        s = fmaf(sdot[tt], v[idx], s);
        const float val = s / kp[idx];
        const __nv_bfloat16 hh = __float2bfloat16(val);
        athi[idx] = hh;
        atlo[idx] = __float2bfloat16(val - __bfloat162float(hh));
    }
}

// ---------------------------------------------------------------------------
// kernel_launch
// Fused-weight formulation: q' = exp(x @ (Wq@Fq) + c), k' = exp(x @ (Wk@Fk) + c)
// ---------------------------------------------------------------------------
extern "C" void kernel_launch(void* const* d_in, const int* in_sizes, int n_in,
                              void* d_out, int out_size)
{
    (void)in_sizes; (void)n_in; (void)out_size;
    const float* x  = (const float*)d_in[0];
    const float* wq = (const float*)d_in[1];
    const float* wk = (const float*)d_in[2];
    const float* wv = (const float*)d_in[3];
    const float* wo = (const float*)d_in[4];
    const float* fq = (const float*)d_in[5];
    const float* fk = (const float*)d_in[6];
    float* out = (float*)d_out;

    void *xhi, *xlo, *qhi, *qlo, *khi, *klo, *athi, *atlo, *wthi, *wtlo;
    void *v4, *qp4, *kp4, *dt, *pt;
    cudaGetSymbolAddress(&xhi,  g_xhi);  cudaGetSymbolAddress(&xlo,  g_xlo);
    cudaGetSymbolAddress(&qhi,  g_qhi);  cudaGetSymbolAddress(&qlo,  g_qlo);
    cudaGetSymbolAddress(&khi,  g_khi);  cudaGetSymbolAddress(&klo,  g_klo);
    cudaGetSymbolAddress(&athi, g_athi); cudaGetSymbolAddress(&atlo, g_atlo);
    cudaGetSymbolAddress(&wthi, g_wthi); cudaGetSymbolAddress(&wtlo, g_wtlo);
    cudaGetSymbolAddress(&v4,  g_v4);
    cudaGetSymbolAddress(&qp4, g_qp4);
    cudaGetSymbolAddress(&kp4, g_kp4);
    cudaGetSymbolAddress(&dt,  g_dot);
    cudaGetSymbolAddress(&pt,  g_part);

    typedef __nv_bfloat16 bf;
    bf* WThi = (bf*)wthi;  bf* WTlo = (bf*)wtlo;
    float* vF  = (float*)v4;
    float* qpF = (float*)qp4;
    float* kpF = (float*)kp4;
    float* dotF = (float*)dt;
    float* partF = (float*)pt;

    cudaFuncSetAttribute(mma_gemm<0>, cudaFuncAttributeMaxDynamicSharedMemorySize, SMEM_SZ);
    cudaFuncSetAttribute(mma_gemm<1>, cudaFuncAttributeMaxDynamicSharedMemorySize, SMEM_SZ);
    cudaFuncSetAttribute(mma_gemm<2>, cudaFuncAttributeMaxDynamicSharedMemorySize, SMEM_SZ);

    // slot map in WThi/WTlo: 0=Fq^T 1=Fk^T 2=Wv^T 3=Wo^T 4=Wq(split) 5=Wk(split)
    bf* FqT_h = WThi + 0 * (size_t)KN;  bf* FqT_l = WTlo + 0 * (size_t)KN;
    bf* FkT_h = WThi + 1 * (size_t)KN;  bf* FkT_l = WTlo + 1 * (size_t)KN;
    bf* WvT_h = WThi + 2 * (size_t)KN;  bf* WvT_l = WTlo + 2 * (size_t)KN;
    bf* WoT_h = WThi + 3 * (size_t)KN;  bf* WoT_l = WTlo + 3 * (size_t)KN;
    bf* Wq_h  = WThi + 4 * (size_t)KN;  bf* Wq_l  = WTlo + 4 * (size_t)KN;
    bf* Wk_h  = WThi + 5 * (size_t)KN;  bf* Wk_l  = WTlo + 5 * (size_t)KN;

    // 1) splits + transposes
    split_fp32<<<(MK / 4 + 255) / 256, 256>>>((const float4*)x,
        (__nv_bfloat162*)xhi, (__nv_bfloat162*)xlo, MK / 4);
    split_fp32<<<(KN / 4 + 255) / 256, 256>>>((const float4*)wq,
        (__nv_bfloat162*)Wq_h, (__nv_bfloat162*)Wq_l, KN / 4);
    split_fp32<<<(KN / 4 + 255) / 256, 256>>>((const float4*)wk,
        (__nv_bfloat162*)Wk_h, (__nv_bfloat162*)Wk_l, KN / 4);
    const dim3 tg(Dc / 32, Dc / 32);
    transpose_split<<<tg, 256>>>(fq, FqT_h, FqT_l);
    transpose_split<<<tg, 256>>>(fk, FkT_h, FkT_l);
    transpose_split<<<tg, 256>>>(wv, WvT_h, WvT_l);
    transpose_split<<<tg, 256>>>(wo, WoT_h, WoT_l);

    const dim3 gsmall(Dc / 128, Dc / 128);   // (16, 16)
    const dim3 gbig  (Dc / 128, Mc / 128);   // (16, 64)

    // 2) fused weights: W'q^T = Fq^T @ Wq^T  (C[m][n] = sum_k Fq[k][m] Wq[n][k])
    mma_gemm<2><<<gsmall, 256, SMEM_SZ>>>(FqT_h, FqT_l, Wq_h, Wq_l,
                                          nullptr, (bf*)qhi, (bf*)qlo);
    mma_gemm<2><<<gsmall, 256, SMEM_SZ>>>(FkT_h, FkT_l, Wk_h, Wk_l,
                                          nullptr, (bf*)khi, (bf*)klo);

    // 3) feature maps with fused exp: qp = exp(x @ W'q + c), kp = exp(x @ W'k + c)
    mma_gemm<1><<<gbig, 256, SMEM_SZ>>>((bf*)xhi, (bf*)xlo,
        (bf*)qhi, (bf*)qlo, qpF, nullptr, nullptr);
    mma_gemm<1><<<gbig, 256, SMEM_SZ>>>((bf*)xhi, (bf*)xlo,
        (bf*)khi, (bf*)klo, kpF, nullptr, nullptr);

    // 4) v projection
    mma_gemm<0><<<gbig, 256, SMEM_SZ>>>((bf*)xhi, (bf*)xlo,
        WvT_h, WvT_l, vF, nullptr, nullptr);

    // 5) dot + chunked scan (writes at in bf16 hi/lo)
    dot_kernel<<<BHTc / 8, 256>>>(qpF, kpF, dotF);
    scanA<<<dim3(CT, BHc), 128>>>(dotF, vF, partF);
    scanB<<<BHc, 128>>>(partF);
    scanC<<<dim3(CT, BHc), 128>>>(dotF, vF, kpF, partF, (bf*)athi, (bf*)atlo);

    // 6) output projection
    mma_gemm<0><<<gbig, 256, SMEM_SZ>>>((bf*)athi, (bf*)atlo,
        WoT_h, WoT_l, out, nullptr, nullptr);
}